// round 1
// baseline (speedup 1.0000x reference)
#include <cuda_runtime.h>
#include <cstdint>

#define NN 100000
#define NE 1600000
#define FF 128
#define CC 64

// ---------------- scratch (static device globals; no allocation) ----------------
__device__ int   g_cnt[NN];
__device__ int   g_rowptr[NN + 1];
__device__ int   g_cursor[NN];
__device__ int   g_col[NE];
__device__ float g_mean[(size_t)NN * 128];  // layer1 mean(x); reused as PQ for layer2
__device__ float g_h[(size_t)NN * 128];     // hidden activations

// ---------------- CSR build ----------------
__global__ void k_zero_cnt() {
    int i = blockIdx.x * blockDim.x + threadIdx.x;
    if (i < NN) g_cnt[i] = 0;
}

__global__ void k_count(const int* __restrict__ dst) {
    int e = blockIdx.x * blockDim.x + threadIdx.x;
    if (e < NE) atomicAdd(&g_cnt[dst[e]], 1);
}

__global__ void k_scan() {
    __shared__ int sh[1024];
    const int T = 1024;
    int t = threadIdx.x;
    const int chunk = (NN + T - 1) / T;   // 98
    int b = t * chunk;
    int e = min(b + chunk, NN);
    int s = 0;
    for (int i = b; i < e; i++) s += g_cnt[i];
    sh[t] = s;
    __syncthreads();
    for (int off = 1; off < T; off <<= 1) {
        int v = (t >= off) ? sh[t - off] : 0;
        __syncthreads();
        sh[t] += v;
        __syncthreads();
    }
    int run = sh[t] - s;   // exclusive prefix
    for (int i = b; i < e; i++) {
        int c = g_cnt[i];
        g_rowptr[i] = run;
        g_cursor[i] = run;
        run += c;
    }
    if (t == T - 1) g_rowptr[NN] = run;
}

__global__ void k_fill(const int* __restrict__ src, const int* __restrict__ dst) {
    int e = blockIdx.x * blockDim.x + threadIdx.x;
    if (e < NE) {
        int d = dst[e];
        int pos = atomicAdd(&g_cursor[d], 1);
        g_col[pos] = src[e];
    }
}

// ---------------- aggregation: mean of 128-wide rows, one warp per node ----------------
__global__ void k_agg128(const float* __restrict__ X) {
    int node = blockIdx.x * (blockDim.x >> 5) + (threadIdx.x >> 5);
    if (node >= NN) return;
    int lane = threadIdx.x & 31;
    int b = g_rowptr[node], e = g_rowptr[node + 1];
    float4 acc = make_float4(0.f, 0.f, 0.f, 0.f);
    int i = b;
    for (; i + 4 <= e; i += 4) {
        int u0 = g_col[i + 0], u1 = g_col[i + 1], u2 = g_col[i + 2], u3 = g_col[i + 3];
        float4 v0 = *((const float4*)(X + (size_t)u0 * FF) + lane);
        float4 v1 = *((const float4*)(X + (size_t)u1 * FF) + lane);
        float4 v2 = *((const float4*)(X + (size_t)u2 * FF) + lane);
        float4 v3 = *((const float4*)(X + (size_t)u3 * FF) + lane);
        acc.x += (v0.x + v1.x) + (v2.x + v3.x);
        acc.y += (v0.y + v1.y) + (v2.y + v3.y);
        acc.z += (v0.z + v1.z) + (v2.z + v3.z);
        acc.w += (v0.w + v1.w) + (v2.w + v3.w);
    }
    for (; i < e; i++) {
        int u = g_col[i];
        float4 v = *((const float4*)(X + (size_t)u * FF) + lane);
        acc.x += v.x; acc.y += v.y; acc.z += v.z; acc.w += v.w;
    }
    float inv = 1.f / (float)max(e - b, 1);
    float4 r = make_float4(acc.x * inv, acc.y * inv, acc.z * inv, acc.w * inv);
    *((float4*)(g_mean + (size_t)node * FF) + lane) = r;
}

// ---------------- GEMM: C[BMx64] tile += A[mtile,128] @ W[64rows,128]^T ----------------
#define BM 128
#define BN 64
#define BK 32

__device__ __forceinline__ void gemm_accum(
    const float* __restrict__ A,     // [NN x 128] row-major
    const float* __restrict__ W,     // >=64 rows x 128, row-major (pre-offset)
    int mbase, int tid, float (&acc)[8][4],
    float (*As)[BK + 1], float (*Ws)[BN])
{
    for (int kb = 0; kb < 128; kb += BK) {
        // load A tile (128 rows x 32 cols), zero-fill past NN
#pragma unroll
        for (int j = 0; j < 4; j++) {
            int idx = tid + j * 256;
            int r = idx >> 3, c4 = idx & 7;
            int m = mbase + r;
            float4 v = make_float4(0.f, 0.f, 0.f, 0.f);
            if (m < NN) v = *(const float4*)(A + (size_t)m * 128 + kb + c4 * 4);
            float* d = &As[r][c4 * 4];
            d[0] = v.x; d[1] = v.y; d[2] = v.z; d[3] = v.w;
        }
        // load W tile transposed: Ws[k][n] = W[n][kb+k]
        {
            int n = tid >> 2;            // 0..63
            int k0 = (tid & 3) * 8;      // 0,8,16,24
            const float* wp = W + (size_t)n * 128 + kb + k0;
#pragma unroll
            for (int i = 0; i < 8; i++) Ws[k0 + i][n] = wp[i];
        }
        __syncthreads();
        int m0 = (tid >> 4) * 8;
        int n0 = (tid & 15) * 4;
#pragma unroll
        for (int k = 0; k < BK; k++) {
            float4 w = *(const float4*)&Ws[k][n0];
#pragma unroll
            for (int r = 0; r < 8; r++) {
                float a = As[m0 + r][k];
                acc[r][0] += a * w.x;
                acc[r][1] += a * w.y;
                acc[r][2] += a * w.z;
                acc[r][3] += a * w.w;
            }
        }
        __syncthreads();
    }
}

// layer 1: h = relu(mean @ W1l^T + x @ W1r^T + b1l)   (output 128 cols; blockIdx.y = col half)
__global__ void __launch_bounds__(256)
k_gemm1(const float* __restrict__ X,
        const float* __restrict__ W1l, const float* __restrict__ W1r,
        const float* __restrict__ b1l)
{
    __shared__ float As[BM][BK + 1];
    __shared__ float Ws[BK][BN];
    int tid = threadIdx.x;
    int mbase = blockIdx.x * BM;
    int nb = blockIdx.y * BN;
    float acc[8][4];
#pragma unroll
    for (int r = 0; r < 8; r++)
#pragma unroll
        for (int c = 0; c < 4; c++) acc[r][c] = 0.f;

    gemm_accum(g_mean, W1l + (size_t)nb * 128, mbase, tid, acc, As, Ws);
    gemm_accum(X,      W1r + (size_t)nb * 128, mbase, tid, acc, As, Ws);

    int m0 = mbase + (tid >> 4) * 8;
    int n0 = nb + (tid & 15) * 4;
    float4 bias = *(const float4*)(b1l + n0);
#pragma unroll
    for (int r = 0; r < 8; r++) {
        int m = m0 + r;
        if (m < NN) {
            float4 o;
            o.x = fmaxf(acc[r][0] + bias.x, 0.f);
            o.y = fmaxf(acc[r][1] + bias.y, 0.f);
            o.z = fmaxf(acc[r][2] + bias.z, 0.f);
            o.w = fmaxf(acc[r][3] + bias.w, 0.f);
            *(float4*)(g_h + (size_t)m * 128 + n0) = o;
        }
    }
}

// layer 2 projections: PQ[:,0:64] = h @ W2l^T ; PQ[:,64:128] = h @ W2r^T + b2l
__global__ void __launch_bounds__(256)
k_gemm2(const float* __restrict__ W2l, const float* __restrict__ W2r,
        const float* __restrict__ b2l)
{
    __shared__ float As[BM][BK + 1];
    __shared__ float Ws[BK][BN];
    int tid = threadIdx.x;
    int mbase = blockIdx.x * BM;
    int half = blockIdx.y;
    const float* W = half ? W2r : W2l;
    float acc[8][4];
#pragma unroll
    for (int r = 0; r < 8; r++)
#pragma unroll
        for (int c = 0; c < 4; c++) acc[r][c] = 0.f;

    gemm_accum(g_h, W, mbase, tid, acc, As, Ws);

    int m0 = mbase + (tid >> 4) * 8;
    int n0 = (tid & 15) * 4;
    float4 bias = make_float4(0.f, 0.f, 0.f, 0.f);
    if (half) bias = *(const float4*)(b2l + n0);
#pragma unroll
    for (int r = 0; r < 8; r++) {
        int m = m0 + r;
        if (m < NN) {
            float4 o;
            o.x = acc[r][0] + bias.x;
            o.y = acc[r][1] + bias.y;
            o.z = acc[r][2] + bias.z;
            o.w = acc[r][3] + bias.w;
            *(float4*)(g_mean + (size_t)m * 128 + half * 64 + n0) = o;
        }
    }
}

// ---------------- final: out = log_softmax(mean_agg(p) + q), one warp per node ----------------
__global__ void k_final(float* __restrict__ out) {
    int node = blockIdx.x * (blockDim.x >> 5) + (threadIdx.x >> 5);
    if (node >= NN) return;
    int lane = threadIdx.x & 31;
    int b = g_rowptr[node], e = g_rowptr[node + 1];
    float2 acc = make_float2(0.f, 0.f);
    const float* PQ = g_mean;
    int i = b;
    for (; i + 4 <= e; i += 4) {
        int u0 = g_col[i + 0], u1 = g_col[i + 1], u2 = g_col[i + 2], u3 = g_col[i + 3];
        float2 v0 = *((const float2*)(PQ + (size_t)u0 * 128) + lane);
        float2 v1 = *((const float2*)(PQ + (size_t)u1 * 128) + lane);
        float2 v2 = *((const float2*)(PQ + (size_t)u2 * 128) + lane);
        float2 v3 = *((const float2*)(PQ + (size_t)u3 * 128) + lane);
        acc.x += (v0.x + v1.x) + (v2.x + v3.x);
        acc.y += (v0.y + v1.y) + (v2.y + v3.y);
    }
    for (; i < e; i++) {
        int u = g_col[i];
        float2 v = *((const float2*)(PQ + (size_t)u * 128) + lane);
        acc.x += v.x; acc.y += v.y;
    }
    float inv = 1.f / (float)max(e - b, 1);
    float2 q = *((const float2*)(PQ + (size_t)node * 128 + 64) + lane);
    float r0 = acc.x * inv + q.x;
    float r1 = acc.y * inv + q.y;

    // log_softmax over 64 values (2 per lane)
    float mx = fmaxf(r0, r1);
#pragma unroll
    for (int off = 16; off > 0; off >>= 1)
        mx = fmaxf(mx, __shfl_xor_sync(0xffffffffu, mx, off));
    float se = expf(r0 - mx) + expf(r1 - mx);
#pragma unroll
    for (int off = 16; off > 0; off >>= 1)
        se += __shfl_xor_sync(0xffffffffu, se, off);
    float l = logf(se);
    float2 o = make_float2(r0 - mx - l, r1 - mx - l);
    *((float2*)(out + (size_t)node * CC) + lane) = o;
}

// ---------------- launch ----------------
extern "C" void kernel_launch(void* const* d_in, const int* in_sizes, int n_in,
                              void* d_out, int out_size) {
    const float* x   = (const float*)d_in[0];
    const int*   ei  = (const int*)d_in[1];     // [2, NE] int32 (JAX x64 disabled)
    const int*   src = ei;
    const int*   dst = ei + NE;
    const float* W1l = (const float*)d_in[2];
    const float* b1l = (const float*)d_in[3];
    const float* W1r = (const float*)d_in[4];
    const float* W2l = (const float*)d_in[5];
    const float* b2l = (const float*)d_in[6];
    const float* W2r = (const float*)d_in[7];
    float* out = (float*)d_out;

    // CSR build (by destination)
    k_zero_cnt<<<(NN + 255) / 256, 256>>>();
    k_count<<<(NE + 255) / 256, 256>>>(dst);
    k_scan<<<1, 1024>>>();
    k_fill<<<(NE + 255) / 256, 256>>>(src, dst);

    // layer 1
    k_agg128<<<(NN + 7) / 8, 256>>>(x);                       // g_mean = mean(x)
    dim3 g1((NN + BM - 1) / BM, 2);
    k_gemm1<<<g1, 256>>>(x, W1l, W1r, b1l);                   // g_h = relu(...)

    // layer 2 (project before aggregating: mean commutes with linear map)
    dim3 g2((NN + BM - 1) / BM, 2);
    k_gemm2<<<g2, 256>>>(W2l, W2r, b2l);                      // g_mean = [p | q]
    k_final<<<(NN + 7) / 8, 256>>>(out);                      // mean(p)+q, log_softmax
}